// round 17
// baseline (speedup 1.0000x reference)
#include <cuda_runtime.h>
#include <cstdint>

#define NSMP   32768
#define TSTEPS 512
#define NTHR   224      // 7 warps/CTA
#define NCTA   293      // 293*7 = 2051 warps x 16 samples >= 32768; 2 CTAs/SM

typedef unsigned int uint;

// ---------------- smem layout (32-bit word offsets) ----------------
#define OFF_DT 0        // 511 dt
#define OFF_SQ 512      // 511 sqrt(dt)
#define OFF_B  1024     // [net][256]: b1@0 b2@64 b3@128 b4pad@192(8)
#define OFF_W1 1536     // [net][half][nj][lane]          net stride 512 (hi+lo)
#define OFF_W4 2560     // [net][half][ktp][lane][4]      net stride 512 (hi+lo)
#define OFF_W2 3584     // [net][ktp][nj][lane][4]        net stride 2048 (hi only)
#define OFF_W3 7680
#define SMEM_WORDS 11776
#define SMEM_BYTES (SMEM_WORDS * 4)

// ---------------- math helpers ----------------
// lipswish = 0.909*x*sigmoid(x) = 0.4545*x*(1 + tanh(0.5x)): 1 MUFU + 3 ops
__device__ __forceinline__ float lipswish(float x) {
    float t;
    asm("tanh.approx.f32 %0, %1;" : "=f"(t) : "f"(0.5f * x));
    return 0.4545f * x * (1.0f + t);
}
__device__ __forceinline__ float softplus_acc(float x) {
    return fmaxf(x, 0.0f) + log1pf(__expf(-fabsf(x)));
}
// pack (x0, x1) -> single bf16x2 (lower=x0)
__device__ __forceinline__ uint pack_bf16x2(float x0, float x1) {
    uint h;
    asm("cvt.rn.bf16x2.f32 %0, %1, %2;" : "=r"(h) : "f"(x1), "f"(x0));
    return h;
}
// pack (x0, x1) -> hi bf16x2 (lower=x0) and lo (residual) bf16x2 (y, W1, W4)
__device__ __forceinline__ void split2(float x0, float x1, uint& h, uint& l) {
    asm("cvt.rn.bf16x2.f32 %0, %1, %2;" : "=r"(h) : "f"(x1), "f"(x0));
    float h0 = __uint_as_float(h << 16);
    float h1 = __uint_as_float(h & 0xFFFF0000u);
    asm("cvt.rn.bf16x2.f32 %0, %1, %2;" : "=r"(l) : "f"(x1 - h1), "f"(x0 - h0));
}

// ---------------- mma.sync wrappers (base sm_80+ PTX, OK on sm_103) ----------------
__device__ __forceinline__ void mma16(float* d, const uint* a, uint b0, uint b1) {
    asm("mma.sync.aligned.m16n8k16.row.col.f32.bf16.bf16.f32 "
        "{%0,%1,%2,%3},{%4,%5,%6,%7},{%8,%9},{%0,%1,%2,%3};"
        : "+f"(d[0]), "+f"(d[1]), "+f"(d[2]), "+f"(d[3])
        : "r"(a[0]), "r"(a[1]), "r"(a[2]), "r"(a[3]), "r"(b0), "r"(b1));
}
__device__ __forceinline__ void mma8(float* d, uint a0, uint a1, uint b0) {
    asm("mma.sync.aligned.m16n8k8.row.col.f32.bf16.bf16.f32 "
        "{%0,%1,%2,%3},{%4,%5},{%6},{%0,%1,%2,%3};"
        : "+f"(d[0]), "+f"(d[1]), "+f"(d[2]), "+f"(d[3])
        : "r"(a0), "r"(a1), "r"(b0));
}

// D fragments (8 x m16n8) -> lipswish -> bf16 -> A fragments of next layer.
__device__ __forceinline__ void epilogue(float d[8][4], uint Ahi[4][4]) {
#pragma unroll
    for (int nj = 0; nj < 8; nj++) {
        float a0 = lipswish(d[nj][0]);
        float a1 = lipswish(d[nj][1]);
        float a2 = lipswish(d[nj][2]);
        float a3 = lipswish(d[nj][3]);
        uint h01 = pack_bf16x2(a0, a1);
        uint h23 = pack_bf16x2(a2, a3);
        int kt = nj >> 1;
        if ((nj & 1) == 0) {
            Ahi[kt][0] = h01;
            Ahi[kt][1] = h23;
        } else {
            Ahi[kt][2] = h01;
            Ahi[kt][3] = h23;
        }
    }
}

// Fused dual-net 64->64 hidden layer (M=16): f and g MMAs interleaved so the
// tensor pipe of one net overlaps the epilogue MUFU/fma of the other.
__device__ __forceinline__ void hidden_fg(const uint* __restrict__ usm,
                                          int wbF, int wbG,
                                          const float* __restrict__ bF,
                                          const float* __restrict__ bG,
                                          uint AF[4][4], uint AG[4][4],
                                          int lane, int tig) {
    float dF[8][4], dG[8][4];
#pragma unroll
    for (int nj = 0; nj < 8; nj++) {
        float2 bf = *(const float2*)(bF + nj * 8 + 2 * tig);
        float2 bg = *(const float2*)(bG + nj * 8 + 2 * tig);
        dF[nj][0] = bf.x; dF[nj][1] = bf.y; dF[nj][2] = bf.x; dF[nj][3] = bf.y;
        dG[nj][0] = bg.x; dG[nj][1] = bg.y; dG[nj][2] = bg.x; dG[nj][3] = bg.y;
    }
#pragma unroll
    for (int ktp = 0; ktp < 2; ktp++)
#pragma unroll
        for (int nj = 0; nj < 8; nj++) {
            int pos = ((ktp * 8 + nj) * 32 + lane) * 4;
            uint4 wf = *(const uint4*)(usm + wbF + pos);
            uint4 wg = *(const uint4*)(usm + wbG + pos);
            mma16(dF[nj], AF[2 * ktp],     wf.x, wf.y);
            mma16(dG[nj], AG[2 * ktp],     wg.x, wg.y);
            mma16(dF[nj], AF[2 * ktp + 1], wf.z, wf.w);
            mma16(dG[nj], AG[2 * ktp + 1], wg.z, wg.w);
        }
    epilogue(dF, AF);
    epilogue(dG, AG);
}

struct Params {
    const float* p[19];
    float* out;
};

__global__ __launch_bounds__(NTHR, 2) void sde_kernel(Params P) {
    extern __shared__ float smf[];
    uint* usm = (uint*)smf;
    const int tid = threadIdx.x;

    // ---------------- staging ----------------
    for (int i = tid; i < TSTEPS - 1; i += NTHR) {
        float dt = P.p[1][i + 1] - P.p[1][i];
        smf[OFF_DT + i] = dt;
        smf[OFF_SQ + i] = sqrtf(dt);
    }
    // biases (b4 padded to 8 with zeros)
    {
        const int bsrc[8] = {4, 6, 8, 10, 12, 14, 16, 18};
        for (int net = 0; net < 2; net++)
            for (int a = 0; a < 4; a++) {
                int cnt = (a < 3) ? 64 : 8;
                const float* src = P.p[bsrc[net * 4 + a]];
                for (int i = tid; i < cnt; i += NTHR)
                    smf[OFF_B + net * 256 + a * 64 + i] =
                        (a < 3 || i < 4) ? src[i] : 0.0f;
            }
    }
    // W2/W3 fragment-linear staging (bf16 hi only)
    {
        const float* Ws[4] = {P.p[5], P.p[13], P.p[7], P.p[15]};
        const int    bs[4] = {OFF_W2, OFF_W2 + 2048, OFF_W3, OFF_W3 + 2048};
        for (int nl = 0; nl < 4; nl++) {
            const float* S = Ws[nl];
            int base = bs[nl];
            for (int idx = tid; idx < 2048; idx += NTHR) {
                int w = idx & 3, lane = (idx >> 2) & 31;
                int nj = (idx >> 7) & 7, ktp = idx >> 10;
                int g = lane >> 2, tg = lane & 3;
                int kt = ktp * 2 + (w >> 1), breg = w & 1;
                int n = nj * 8 + g;
                int k0 = kt * 16 + 2 * tg + 8 * breg;
                usm[base + idx] = pack_bf16x2(S[k0 * 64 + n], S[(k0 + 1) * 64 + n]);
            }
        }
    }
    // W1 staging (K padded 4->8, hi+lo)
    {
        const float* W1s[2] = {P.p[3], P.p[11]};
        for (int net = 0; net < 2; net++)
            for (int idx = tid; idx < 256; idx += NTHR) {
                int lane = idx & 31, nj = idx >> 5;
                int g = lane >> 2, tg = lane & 3;
                int n = nj * 8 + g;
                int k0 = 2 * tg;
                float v0 = (k0 < 4)     ? W1s[net][k0 * 64 + n]       : 0.0f;
                float v1 = (k0 + 1 < 4) ? W1s[net][(k0 + 1) * 64 + n] : 0.0f;
                uint hi, lo;
                split2(v0, v1, hi, lo);
                usm[OFF_W1 + net * 512 + idx] = hi;
                usm[OFF_W1 + net * 512 + 256 + idx] = lo;
            }
    }
    // W4 staging (N padded 4->8, hi+lo)
    {
        const float* W4s[2] = {P.p[9], P.p[17]};
        for (int net = 0; net < 2; net++)
            for (int idx = tid; idx < 256; idx += NTHR) {
                int w = idx & 3, lane = (idx >> 2) & 31, ktp = idx >> 7;
                int g = lane >> 2, tg = lane & 3;
                int kt = ktp * 2 + (w >> 1), breg = w & 1;
                int n = g;
                int k0 = kt * 16 + 2 * tg + 8 * breg;
                float v0 = (n < 4) ? W4s[net][k0 * 4 + n]       : 0.0f;
                float v1 = (n < 4) ? W4s[net][(k0 + 1) * 4 + n] : 0.0f;
                uint hi, lo;
                split2(v0, v1, hi, lo);
                usm[OFF_W4 + net * 512 + idx] = hi;
                usm[OFF_W4 + net * 512 + 256 + idx] = lo;
            }
    }
    __syncthreads();

    // ---------------- per-warp fragment-domain SDE loop (16 samples/warp) ----------------
    const int lane = tid & 31;
    const int g = lane >> 2, tig = lane & 3;
    const int gw = blockIdx.x * (NTHR / 32) + (tid >> 5);
    const int sbase = gw * 16;
    if (sbase >= NSMP) return;          // tail warps (3 of 2051) exit whole
    const bool ldok = (tig < 2);

    const float* y0 = P.p[0];
    const float* nz = P.p[2];
    float* out = P.out;

    const float* bF = smf + OFF_B;
    const float* bG = smf + OFF_B + 256;

    // y in D-fragment form: y[0..3] = rows (sbase+g, +8) x cols (2tig, 2tig+1)
    float y[4];
    const int r0 = sbase + g;
    if (ldok) {
        float2 v0 = *(const float2*)(y0 + r0 * 4 + 2 * tig);
        float2 v1 = *(const float2*)(y0 + (r0 + 8) * 4 + 2 * tig);
        y[0] = v0.x; y[1] = v0.y; y[2] = v1.x; y[3] = v1.y;
        *(float2*)(out + (size_t)r0 * TSTEPS * 4 + 2 * tig) = v0;
        *(float2*)(out + (size_t)(r0 + 8) * TSTEPS * 4 + 2 * tig) = v1;
    } else {
        y[0] = y[1] = y[2] = y[3] = 0.0f;
    }
    uint yhi[2], ylo[2];
    split2(y[0], y[1], yhi[0], ylo[0]);
    split2(y[2], y[3], yhi[1], ylo[1]);

    for (int t = 0; t < TSTEPS - 1; t++) {
        float dwv[4];
        if (ldok) {
            const float* b = nz + ((size_t)t * NSMP) * 4;
            float2 v0 = *(const float2*)(b + r0 * 4 + 2 * tig);
            float2 v1 = *(const float2*)(b + (r0 + 8) * 4 + 2 * tig);
            dwv[0] = v0.x; dwv[1] = v0.y; dwv[2] = v1.x; dwv[3] = v1.y;
        } else {
            dwv[0] = dwv[1] = dwv[2] = dwv[3] = 0.0f;
        }

        uint AF[4][4], AG[4][4];
        // ---- dual L1: m16n8k8, K=4 padded to 8, 3-product y-split ----
        {
            float dF[8][4], dG[8][4];
#pragma unroll
            for (int nj = 0; nj < 8; nj++) {
                float2 bf = *(const float2*)(bF + nj * 8 + 2 * tig);
                float2 bg = *(const float2*)(bG + nj * 8 + 2 * tig);
                dF[nj][0] = bf.x; dF[nj][1] = bf.y; dF[nj][2] = bf.x; dF[nj][3] = bf.y;
                dG[nj][0] = bg.x; dG[nj][1] = bg.y; dG[nj][2] = bg.x; dG[nj][3] = bg.y;
            }
#pragma unroll
            for (int nj = 0; nj < 8; nj++) {
                uint whF = usm[OFF_W1 + nj * 32 + lane];
                uint wlF = usm[OFF_W1 + 256 + nj * 32 + lane];
                uint whG = usm[OFF_W1 + 512 + nj * 32 + lane];
                uint wlG = usm[OFF_W1 + 768 + nj * 32 + lane];
                mma8(dF[nj], yhi[0], yhi[1], whF);
                mma8(dG[nj], yhi[0], yhi[1], whG);
                mma8(dF[nj], yhi[0], yhi[1], wlF);
                mma8(dG[nj], yhi[0], yhi[1], wlG);
                mma8(dF[nj], ylo[0], ylo[1], whF);
                mma8(dG[nj], ylo[0], ylo[1], whG);
            }
            epilogue(dF, AF);
            epilogue(dG, AG);
        }
        // ---- dual hidden layers ----
        hidden_fg(usm, OFF_W2, OFF_W2 + 2048, bF + 64,  bG + 64,  AF, AG, lane, tig);
        hidden_fg(usm, OFF_W3, OFF_W3 + 2048, bF + 128, bG + 128, AF, AG, lane, tig);
        // ---- dual L4: m16n8k16, N=4 padded to 8, weight hi+lo ----
        float df[4], dg[4];
        {
            float2 bbf = *(const float2*)(bF + 192 + 2 * tig);
            float2 bbg = *(const float2*)(bG + 192 + 2 * tig);
            df[0] = bbf.x; df[1] = bbf.y; df[2] = bbf.x; df[3] = bbf.y;
            dg[0] = bbg.x; dg[1] = bbg.y; dg[2] = bbg.x; dg[3] = bbg.y;
#pragma unroll
            for (int ktp = 0; ktp < 2; ktp++) {
                int pos = (ktp * 32 + lane) * 4;
                uint4 whF = *(const uint4*)(usm + OFF_W4 + pos);
                uint4 wlF = *(const uint4*)(usm + OFF_W4 + 256 + pos);
                uint4 whG = *(const uint4*)(usm + OFF_W4 + 512 + pos);
                uint4 wlG = *(const uint4*)(usm + OFF_W4 + 768 + pos);
                mma16(df, AF[2 * ktp],     whF.x, whF.y);
                mma16(dg, AG[2 * ktp],     whG.x, whG.y);
                mma16(df, AF[2 * ktp],     wlF.x, wlF.y);
                mma16(dg, AG[2 * ktp],     wlG.x, wlG.y);
                mma16(df, AF[2 * ktp + 1], whF.z, whF.w);
                mma16(dg, AG[2 * ktp + 1], whG.z, whG.w);
                mma16(df, AF[2 * ktp + 1], wlF.z, wlF.w);
                mma16(dg, AG[2 * ktp + 1], wlG.z, wlG.w);
            }
        }

        float dt = smf[OFF_DT + t];
        float sq = smf[OFF_SQ + t];

#pragma unroll
        for (int j = 0; j < 4; j++) {
            float f = fminf(fmaxf(df[j], -100.0f), 100.0f);
            float gg = fmaxf(softplus_acc(dg[j]), 1e-4f);
            y[j] = y[j] + f * dt + gg * sq * dwv[j];
        }

        if (ldok) {
            *(float2*)(out + ((size_t)r0 * TSTEPS + t + 1) * 4 + 2 * tig) =
                make_float2(y[0], y[1]);
            *(float2*)(out + ((size_t)(r0 + 8) * TSTEPS + t + 1) * 4 + 2 * tig) =
                make_float2(y[2], y[3]);
        }
        split2(y[0], y[1], yhi[0], ylo[0]);
        split2(y[2], y[3], yhi[1], ylo[1]);
    }
}

extern "C" void kernel_launch(void* const* d_in, const int* in_sizes, int n_in,
                              void* d_out, int out_size) {
    Params P;
    for (int i = 0; i < 19; i++) P.p[i] = (const float*)d_in[i];
    P.out = (float*)d_out;

    cudaFuncSetAttribute(sde_kernel, cudaFuncAttributeMaxDynamicSharedMemorySize,
                         SMEM_BYTES);
    sde_kernel<<<NCTA, NTHR, SMEM_BYTES>>>(P);
}